// round 10
// baseline (speedup 1.0000x reference)
#include <cuda_runtime.h>

// Problem constants
#define T_STEPS 512
#define B_TOTAL 512
#define I_DIM   32
#define H_DIM   64
#define G_DIM   256   // 4*H
#define HX_DIM  96    // concatenated [h(64); x(32)]
#define NT      8     // num tickers

typedef unsigned long long u64;

__device__ __forceinline__ u64 ffma2(u64 a, u64 b, u64 c) {
    u64 d;
    asm("fma.rn.f32x2 %0, %1, %2, %3;" : "=l"(d) : "l"(a), "l"(b), "l"(c));
    return d;
}
__device__ __forceinline__ u64 mul2(u64 a, u64 b) {
    u64 d;
    asm("mul.rn.f32x2 %0, %1, %2;" : "=l"(d) : "l"(a), "l"(b));
    return d;
}
__device__ __forceinline__ u64 pack2(float lo, float hi) {
    u64 d;
    asm("mov.b64 %0, {%1, %2};" : "=l"(d) : "f"(lo), "f"(hi));
    return d;
}
__device__ __forceinline__ void unpack2(u64 v, float& lo, float& hi) {
    asm("mov.b64 {%0, %1}, %2;" : "=f"(lo), "=f"(hi) : "l"(v));
}
__device__ __forceinline__ float fast_tanh(float x) {
    return 1.0f - 2.0f / (__expf(2.0f * x) + 1.0f);  // stable for large |x|
}

// ---------------------------------------------------------------------------
// Fused LSTM, one-barrier / shfl-combine edition (exp-based activations).
// 256 CTAs x 256 threads, 2 batches/CTA, 2 CTAs/SM.
// Thread (cell = tid>>2, gq = tid&3) owns gate row gq*64+cell:
//   - weights [W_hh|W_ih] k-pair packed in 48 u64 (96 regs)
//   - matvec operands hx[buf][b][96] natural layout, warp-broadcast LDS.128
//   - two chains (batch 0/1); horizontal fold; in-register activation:
//       y = A*rcp(exp(S*x)+1) + B  (lane-uniform instruction stream;
//       sigmoid: A=1,S=-1,B=0; tanh lane gq==2: A=-2,S=2,B=1)
//   - cell combine entirely via 3x shfl_xor within the 4-lane quad
//     (values batch-packed f32x2); lane gq==0 owns c and writes h
//   - gates NEVER touch smem; h/x double-buffered -> ONE barrier per step
//   - x staged by gq==1 lanes via a depth-4 register prefetch ring
// ---------------------------------------------------------------------------
__global__ __launch_bounds__(256, 2) void fused_lstm_kernel(
    const float* __restrict__ x,    const float* __restrict__ w_ih,
    const float* __restrict__ w_hh, const float* __restrict__ b_ih,
    const float* __restrict__ b_hh, const float* __restrict__ w_fc,
    const float* __restrict__ b_fc, float* __restrict__ out)
{
    __shared__ __align__(16) float hx[2][2][HX_DIM];  // [buf][batch][dim]

    const int tid  = threadIdx.x;
    const int cell = tid >> 2;          // 0..63
    const int gq   = tid & 3;           // 0:i 1:f 2:g 3:o
    const int row  = gq * 64 + cell;    // gate row in PyTorch i,f,g,o order
    const int B0   = blockIdx.x * 2;

    // ---- weights for row, k-pair packed into 48 u64 ----
    u64 w2[48];
    {
        const float* rh = w_hh + row * H_DIM;
        #pragma unroll
        for (int k = 0; k < 32; k++) w2[k] = pack2(rh[2 * k], rh[2 * k + 1]);
        const float* ri = w_ih + row * I_DIM;
        #pragma unroll
        for (int i = 0; i < 16; i++) w2[32 + i] = pack2(ri[2 * i], ri[2 * i + 1]);
    }
    const float bias = b_ih[row] + b_hh[row];

    // ---- per-lane activation constants: y = A*rcp(exp(S*x)+1) + B ----
    const float A = (gq == 2) ? -2.0f : 1.0f;
    const float S = (gq == 2) ?  2.0f : -1.0f;
    const float Bc = (gq == 2) ? 1.0f : 0.0f;

    // ---- x staging: gq==1 lanes; batch = cell>>5, dim = cell&31 ----
    const bool is_stage = (gq == 1);
    const int  bq = cell >> 5, iq = cell & 31;
    const float* sx = x + ((size_t)(B0 + bq) * T_STEPS) * I_DIM + iq;
    float xr0 = 0.f, xr1 = 0.f, xr2 = 0.f;

    // ---- init buf0: h = 0, x(0); preload x(1..3) ----
    if (tid < 128) hx[0][tid >> 6][tid & 63] = 0.0f;
    if (is_stage) {
        hx[0][bq][H_DIM + iq] = sx[0];
        xr0 = sx[1 * I_DIM];
        xr1 = sx[2 * I_DIM];
        xr2 = sx[3 * I_DIM];
    }
    u64 c2 = 0ULL;   // cell state, batch-packed (meaningful on gq==0 lanes)
    __syncthreads();

    for (int t = 0; t < T_STEPS; t++) {
        const u64* v0 = (const u64*)hx[t & 1][0];
        const u64* v1 = (const u64*)hx[t & 1][1];

        // ---- k-packed 96-dim dots, both batches (2 indep chains) ----
        u64 acc0 = pack2(bias, 0.0f), acc1 = pack2(bias, 0.0f);
        #pragma unroll
        for (int k = 0; k < 48; k += 2) {
            ulonglong2 a = *(const ulonglong2*)(v0 + k);
            ulonglong2 b = *(const ulonglong2*)(v1 + k);
            acc0 = ffma2(w2[k], a.x, acc0); acc0 = ffma2(w2[k + 1], a.y, acc0);
            acc1 = ffma2(w2[k], b.x, acc1); acc1 = ffma2(w2[k + 1], b.y, acc1);
        }
        float l0, h0, l1, h1;
        unpack2(acc0, l0, h0);
        unpack2(acc1, l1, h1);
        float g0 = l0 + h0;
        float g1 = l1 + h1;

        // ---- in-register activation (lane-uniform exp path) ----
        float y0 = A * __frcp_rn(__expf(S * g0) + 1.0f) + Bc;
        float y1 = A * __frcp_rn(__expf(S * g1) + 1.0f) + Bc;
        u64 y = pack2(y0, y1);

        // ---- quad combine via shfl (lanes: 0=i 1=f 2=g 3=o) ----
        u64 z  = __shfl_xor_sync(0xffffffffu, y, 2);  // gq0: g, gq1: o
        u64 p  = mul2(y, z);                          // gq0: i*g
        u64 fv = __shfl_xor_sync(0xffffffffu, y, 1);  // gq0: f
        c2 = ffma2(fv, c2, p);                        // gq0: c' = f*c + i*g
        u64 ov = __shfl_xor_sync(0xffffffffu, z, 1);  // gq0: o
        float cl, ch;
        unpack2(c2, cl, ch);
        u64 th = pack2(fast_tanh(cl), fast_tanh(ch));
        u64 h2 = mul2(ov, th);                        // gq0: h = o*tanh(c')

        // ---- write next buffer; x stage rides the same phase ----
        float* nb0 = hx[(t + 1) & 1][0];
        float* nb1 = hx[(t + 1) & 1][1];
        if (gq == 0) {
            float hl, hh;
            unpack2(h2, hl, hh);
            nb0[cell] = hl;
            nb1[cell] = hh;
        } else if (is_stage) {
            if (t + 1 < T_STEPS) hx[(t + 1) & 1][bq][H_DIM + iq] = xr0;
            xr0 = xr1; xr1 = xr2;
            if (t + 4 < T_STEPS) xr2 = sx[(size_t)(t + 4) * I_DIM];
        }

        __syncthreads();   // single barrier per step
    }

    // ---- final FC: h_last lives in buf[0] (T even) ----
    if (tid < 2 * NT) {
        int b = tid >> 3, n = tid & 7;
        float s = b_fc[n];
        const float* wf = w_fc + n * H_DIM;
        #pragma unroll
        for (int k = 0; k < H_DIM; k++) s += hx[0][b][k] * wf[k];
        out[(B0 + b) * NT + n] = s;
    }
}

// ---------------------------------------------------------------------------
extern "C" void kernel_launch(void* const* d_in, const int* in_sizes, int n_in,
                              void* d_out, int out_size)
{
    const float* x    = (const float*)d_in[0];
    const float* w_ih = (const float*)d_in[1];
    const float* w_hh = (const float*)d_in[2];
    const float* b_ih = (const float*)d_in[3];
    const float* b_hh = (const float*)d_in[4];
    const float* w_fc = (const float*)d_in[5];
    const float* b_fc = (const float*)d_in[6];
    float* out = (float*)d_out;

    (void)in_sizes; (void)n_in; (void)out_size;

    fused_lstm_kernel<<<B_TOTAL / 2, 256>>>(x, w_ih, w_hh, b_ih, b_hh,
                                            w_fc, b_fc, out);
}